// round 6
// baseline (speedup 1.0000x reference)
#include <cuda_runtime.h>
#include <cstdint>

#define T_ 256
#define D_ 64
#define H_ 256
#define B_ 512
#define ROWSC 8          // batch rows per cluster
#define JH 128           // output columns per CTA
#define NCTA 128
#define THREADS 512      // 128 j * 4 k-quarters

// packed: P[k4 * O + o] = float4{ W[o][4k4+0..3] }  (k-contiguous quads per output col)
__device__ float4 g_w1p[(H_ / 4) * H_];
__device__ float4 g_w2p[(H_ / 4) * H_];
__device__ float4 g_whhp[(H_ / 4) * (3 * H_)];
__device__ float4 g_wihp[(D_ / 4) * (3 * H_)];
__device__ float4 g_woutp[(H_ / 4) * H_];
__device__ float g_dt[T_];

#define N_W1 ((H_ / 4) * H_)
#define N_WHH ((H_ / 4) * (3 * H_))
#define N_WIH ((D_ / 4) * (3 * H_))
#define PK_TOTAL (3 * N_W1 + N_WHH + N_WIH)

__global__ void pack_all_kernel(const float* __restrict__ w1,
                                const float* __restrict__ w2,
                                const float* __restrict__ whh,
                                const float* __restrict__ wih,
                                const float* __restrict__ wout,
                                const float* __restrict__ tps) {
    int idx = blockIdx.x * blockDim.x + threadIdx.x;
    if (idx < T_) {
        g_dt[idx] = (idx == 0) ? (tps[0] - (tps[0] - 0.01f))
                               : (tps[idx] - tps[idx - 1]);
    }
    if (idx >= PK_TOTAL) return;
    const float* src; float4* dst; int O, K, local = idx;
    if (local < N_W1) { src = w1; dst = g_w1p; O = H_; K = H_; }
    else if ((local -= N_W1) < N_W1) { src = w2; dst = g_w2p; O = H_; K = H_; }
    else if ((local -= N_W1) < N_WHH) { src = whh; dst = g_whhp; O = 3 * H_; K = H_; }
    else if ((local -= N_WHH) < N_WIH) { src = wih; dst = g_wihp; O = 3 * H_; K = D_; }
    else { local -= N_WIH; src = wout; dst = g_woutp; O = H_; K = H_; }
    int k4 = local / O;
    int o = local % O;
    const float* s = src + (size_t)o * K + 4 * k4;
    dst[local] = make_float4(s[0], s[1], s[2], s[3]);
}

typedef unsigned long long ull;
__device__ __forceinline__ ull ffma2(ull a, ull b, ull c) {
    ull d; asm("fma.rn.f32x2 %0, %1, %2, %3;" : "=l"(d) : "l"(a), "l"(b), "l"(c)); return d;
}
__device__ __forceinline__ float2 upk2(ull v) {
    float2 f; asm("mov.b64 {%0, %1}, %2;" : "=f"(f.x), "=f"(f.y) : "l"(v)); return f;
}
__device__ __forceinline__ float hadd2(ull v) { float2 f = upk2(v); return f.x + f.y; }
__device__ __forceinline__ float sigmoidf_(float v) { return 1.0f / (1.0f + expf(-v)); }

__device__ __forceinline__ void sts_peer_f32(const void* laddr, uint32_t peer, float v) {
    uint32_t la = (uint32_t)__cvta_generic_to_shared(laddr), ra;
    asm("mapa.shared::cluster.u32 %0, %1, %2;" : "=r"(ra) : "r"(la), "r"(peer));
    asm volatile("st.shared::cluster.b32 [%0], %1;" :: "r"(ra), "r"(__float_as_uint(v)) : "memory");
}
__device__ __forceinline__ void cluster_sync_() {
    asm volatile("barrier.cluster.arrive.aligned;" ::: "memory");
    asm volatile("barrier.cluster.wait.aligned;" ::: "memory");
}

// K-packed GEMM over 8 rows: acc[r] += sum over quad k4 of W[jg][k4]*v[r][k4]
// All lanes of a warp share v addresses (broadcast LDS), weight loads coalesced.
__device__ __forceinline__ void gemm8(ull acc[8], const ulonglong2* __restrict__ wu,
                                      int stride, int jg,
                                      const float* __restrict__ vbuf, int vrow,
                                      int kb, int nkk) {
#pragma unroll 2
    for (int kk = 0; kk < nkk; kk++) {
        int k4 = kb + kk;
        ulonglong2 w = wu[(size_t)k4 * stride + jg];
#pragma unroll
        for (int r = 0; r < 8; r++) {
            ulonglong2 v = *reinterpret_cast<const ulonglong2*>(vbuf + r * vrow + 4 * k4);
            acc[r] = ffma2(w.x, v.x, acc[r]);
            acc[r] = ffma2(w.y, v.y, acc[r]);
        }
    }
}

// smem layout (floats):
// hbuf[8*256] | odebuf[8*256] | a1buf[8*256] | xbuf[8*64] | smk[8] | pad[8] | part[4*32*128]
#define OFF_H 0
#define OFF_ODE 2048
#define OFF_A1 4096
#define OFF_X 6144
#define OFF_MK 6656
#define OFF_PART 6672
#define SMEM_FLOATS (OFF_PART + 4 * 32 * 128)
#define SMEM_BYTES (SMEM_FLOATS * 4)

#define PART(kq, slot, j) spart[((kq) * 32 + (slot)) * JH + (j)]

__global__ void __launch_bounds__(THREADS, 1) __cluster_dims__(2, 1, 1)
gruode_kernel(const float* __restrict__ x,
              const float* __restrict__ mask,
              const float* __restrict__ b_ih,
              const float* __restrict__ b_hh,
              const float* __restrict__ b1,
              const float* __restrict__ b2,
              const float* __restrict__ b_out,
              float* __restrict__ out) {
    extern __shared__ float smem[];
    float* hbuf = smem + OFF_H;
    float* odebuf = smem + OFF_ODE;
    float* a1buf = smem + OFF_A1;
    float* xbuf = smem + OFF_X;
    float* smk = smem + OFF_MK;
    float* spart = smem + OFF_PART;

    const ulonglong2* w1u = reinterpret_cast<const ulonglong2*>(g_w1p);
    const ulonglong2* w2u = reinterpret_cast<const ulonglong2*>(g_w2p);
    const ulonglong2* whhu = reinterpret_cast<const ulonglong2*>(g_whhp);
    const ulonglong2* wihu = reinterpret_cast<const ulonglong2*>(g_wihp);
    const ulonglong2* woutu = reinterpret_cast<const ulonglong2*>(g_woutp);

    const int tid = threadIdx.x;
    const int j0 = tid & (JH - 1);
    const int kq = tid >> 7;           // 0..3
    uint32_t rank;
    asm("mov.u32 %0, %%cluster_ctarank;" : "=r"(rank));
    const uint32_t peer = rank ^ 1u;
    const int jg = (int)rank * JH + j0;
    const int row0 = (blockIdx.x >> 1) * ROWSC;
    const int kb = kq * 16;            // k4 base for K=256 GEMMs (16 quads each)
    const int kbx = kq * 4;            // k4 base for K=64 GEMM (4 quads each)
    const bool comb = (kq == 0);       // combiner threads

    // zero h
    for (int idx = tid; idx < 8 * H_; idx += THREADS) hbuf[idx] = 0.0f;

    // recurrent state (combiner threads only)
    float hcur[8], hlast[8], seen[8], hode[8];
#pragma unroll
    for (int r = 0; r < 8; r++) { hcur[r] = 0.0f; hlast[r] = 0.0f; seen[r] = 0.0f; hode[r] = 0.0f; }

    const float b1j = b1[jg];
    const float b2j = b2[jg];
    const float brz_r = b_ih[jg] + b_hh[jg];
    const float brz_z = b_ih[H_ + jg] + b_hh[H_ + jg];
    const float bin_ = b_ih[2 * H_ + jg];
    const float bhn = b_hh[2 * H_ + jg];

    cluster_sync_();

    for (int t = 0; t < T_; t++) {
        // ---- stage 1: x_t + mask ----
        {
            int r = tid >> 6, c = tid & 63;
            xbuf[tid] = x[((size_t)(row0 + r) * T_ + t) * D_ + c];
        }
        if (tid < ROWSC) smk[tid] = mask[(size_t)(row0 + tid) * T_ + t];

        // ---- stage 2: a1 = tanh(h @ w1^T + b1) ----
        {
            ull acc[8];
#pragma unroll
            for (int r = 0; r < 8; r++) acc[r] = 0ull;
            gemm8(acc, w1u, H_, jg, hbuf, H_, kb, 16);
#pragma unroll
            for (int r = 0; r < 8; r++) PART(kq, r, j0) = hadd2(acc[r]);
            __syncthreads();
            if (comb) {
#pragma unroll
                for (int r = 0; r < 8; r++) {
                    float s = b1j + PART(0, r, j0) + PART(1, r, j0) + PART(2, r, j0) + PART(3, r, j0);
                    float a = tanhf(s);
                    a1buf[r * H_ + jg] = a;
                    sts_peer_f32(&a1buf[r * H_ + jg], peer, a);
                }
            }
        }
        cluster_sync_();

        // ---- stage 3: f = a1 @ w2^T + b2 ; euler ; h_ode ----
        {
            ull acc[8];
#pragma unroll
            for (int r = 0; r < 8; r++) acc[r] = 0ull;
            gemm8(acc, w2u, H_, jg, a1buf, H_, kb, 16);
#pragma unroll
            for (int r = 0; r < 8; r++) PART(kq, r, j0) = hadd2(acc[r]);
            __syncthreads();
            if (comb) {
                const float dtv = g_dt[t];
#pragma unroll
                for (int r = 0; r < 8; r++) {
                    float f = b2j + PART(0, r, j0) + PART(1, r, j0) + PART(2, r, j0) + PART(3, r, j0);
                    float he = hcur[r] + dtv * f;
                    float ho = (seen[r] > 0.0f) ? he : hcur[r];
                    hode[r] = ho;
                    odebuf[r * H_ + jg] = ho;
                    sts_peer_f32(&odebuf[r * H_ + jg], peer, ho);
                }
            }
        }
        cluster_sync_();

        // ---- stage 4: gates ----
        {
            // pass A: r and z gates (gi+gh fused)
            {
                ull aR[8], aZ[8];
#pragma unroll
                for (int r = 0; r < 8; r++) { aR[r] = 0ull; aZ[r] = 0ull; }
#pragma unroll 2
                for (int kk = 0; kk < 16; kk++) {
                    int k4 = kb + kk;
                    ulonglong2 wr = whhu[(size_t)k4 * (3 * H_) + jg];
                    ulonglong2 wz = whhu[(size_t)k4 * (3 * H_) + H_ + jg];
#pragma unroll
                    for (int r = 0; r < 8; r++) {
                        ulonglong2 v = *reinterpret_cast<const ulonglong2*>(odebuf + r * H_ + 4 * k4);
                        aR[r] = ffma2(wr.x, v.x, aR[r]); aR[r] = ffma2(wr.y, v.y, aR[r]);
                        aZ[r] = ffma2(wz.x, v.x, aZ[r]); aZ[r] = ffma2(wz.y, v.y, aZ[r]);
                    }
                }
#pragma unroll
                for (int kk = 0; kk < 4; kk++) {
                    int k4 = kbx + kk;
                    ulonglong2 wr = wihu[(size_t)k4 * (3 * H_) + jg];
                    ulonglong2 wz = wihu[(size_t)k4 * (3 * H_) + H_ + jg];
#pragma unroll
                    for (int r = 0; r < 8; r++) {
                        ulonglong2 v = *reinterpret_cast<const ulonglong2*>(xbuf + r * D_ + 4 * k4);
                        aR[r] = ffma2(wr.x, v.x, aR[r]); aR[r] = ffma2(wr.y, v.y, aR[r]);
                        aZ[r] = ffma2(wz.x, v.x, aZ[r]); aZ[r] = ffma2(wz.y, v.y, aZ[r]);
                    }
                }
#pragma unroll
                for (int r = 0; r < 8; r++) {
                    PART(kq, r, j0) = hadd2(aR[r]);
                    PART(kq, 8 + r, j0) = hadd2(aZ[r]);
                }
            }
            // pass B: n gate — gh_n (from h_ode) and gi_n (from x) kept separate
            {
                ull aN[8], aI[8];
#pragma unroll
                for (int r = 0; r < 8; r++) { aN[r] = 0ull; aI[r] = 0ull; }
                gemm8(aN, whhu, 3 * H_, 2 * H_ + jg, odebuf, H_, kb, 16);
                gemm8(aI, wihu, 3 * H_, 2 * H_ + jg, xbuf, D_, kbx, 4);
#pragma unroll
                for (int r = 0; r < 8; r++) {
                    PART(kq, 16 + r, j0) = hadd2(aN[r]);
                    PART(kq, 24 + r, j0) = hadd2(aI[r]);
                }
            }
            __syncthreads();
            if (comb) {
#pragma unroll
                for (int r = 0; r < 8; r++) {
                    float fr = brz_r + PART(0, r, j0) + PART(1, r, j0) + PART(2, r, j0) + PART(3, r, j0);
                    float fz = brz_z + PART(0, 8 + r, j0) + PART(1, 8 + r, j0) + PART(2, 8 + r, j0) + PART(3, 8 + r, j0);
                    float fn = bhn + PART(0, 16 + r, j0) + PART(1, 16 + r, j0) + PART(2, 16 + r, j0) + PART(3, 16 + r, j0);
                    float fi = bin_ + PART(0, 24 + r, j0) + PART(1, 24 + r, j0) + PART(2, 24 + r, j0) + PART(3, 24 + r, j0);
                    float rg = sigmoidf_(fr);
                    float zg = sigmoidf_(fz);
                    float ng = tanhf(fi + rg * fn);
                    float hrnn = (1.0f - zg) * ng + zg * hode[r];
                    float m = smk[r];
                    float hn = (m > 0.5f) ? hrnn : hode[r];
                    hcur[r] = hn;
                    hlast[r] = (m > 0.5f) ? hn : hlast[r];
                    seen[r] = fmaxf(seen[r], m);
                    hbuf[r * H_ + jg] = hn;
                    sts_peer_f32(&hbuf[r * H_ + jg], peer, hn);
                }
            }
        }
        cluster_sync_();
    }

    // ---- final projection ----
    if (comb) {
#pragma unroll
        for (int r = 0; r < 8; r++) {
            hbuf[r * H_ + jg] = hlast[r];
            sts_peer_f32(&hbuf[r * H_ + jg], peer, hlast[r]);
        }
    }
    cluster_sync_();
    {
        ull acc[8];
#pragma unroll
        for (int r = 0; r < 8; r++) acc[r] = 0ull;
        gemm8(acc, woutu, H_, jg, hbuf, H_, kb, 16);
#pragma unroll
        for (int r = 0; r < 8; r++) PART(kq, r, j0) = hadd2(acc[r]);
        __syncthreads();
        if (comb) {
            const float bo = b_out[jg];
#pragma unroll
            for (int r = 0; r < 8; r++) {
                float s = bo + PART(0, r, j0) + PART(1, r, j0) + PART(2, r, j0) + PART(3, r, j0);
                out[(size_t)(row0 + r) * H_ + jg] = s;
            }
        }
    }
    cluster_sync_();
}

extern "C" void kernel_launch(void* const* d_in, const int* in_sizes, int n_in,
                              void* d_out, int out_size) {
    const float* x     = (const float*)d_in[0];
    const float* tps   = (const float*)d_in[1];
    const float* mask  = (const float*)d_in[2];
    const float* w_ih  = (const float*)d_in[3];
    const float* w_hh  = (const float*)d_in[4];
    const float* b_ih  = (const float*)d_in[5];
    const float* b_hh  = (const float*)d_in[6];
    const float* w1    = (const float*)d_in[7];
    const float* b1    = (const float*)d_in[8];
    const float* w2    = (const float*)d_in[9];
    const float* b2    = (const float*)d_in[10];
    const float* w_out = (const float*)d_in[11];
    const float* b_out = (const float*)d_in[12];
    float* out = (float*)d_out;

    static bool attr_set = false;
    if (!attr_set) {
        cudaFuncSetAttribute(gruode_kernel,
                             cudaFuncAttributeMaxDynamicSharedMemorySize, SMEM_BYTES);
        attr_set = true;
    }

    pack_all_kernel<<<(PK_TOTAL + 255) / 256, 256>>>(w1, w2, w_hh, w_ih, w_out, tps);
    gruode_kernel<<<NCTA, THREADS, SMEM_BYTES>>>(x, mask, b_ih, b_hh, b1, b2, b_out, out);
}

// round 7
// speedup vs baseline: 1.0355x; 1.0355x over previous
#include <cuda_runtime.h>
#include <cstdint>

#define T_ 256
#define D_ 64
#define H_ 256
#define B_ 512
#define ROWSC 8          // batch rows per cluster
#define JH 128           // output columns per CTA
#define NCTA 128
#define THREADS 512      // 128 j * 2 kh * 2 pg

// packed: P[k4 * O + o] = float4{ W[o][4k4+0..3] }
__device__ float4 g_w1p[(H_ / 4) * H_];
__device__ float4 g_w2p[(H_ / 4) * H_];
__device__ float4 g_whhp[(H_ / 4) * (3 * H_)];
__device__ float4 g_wihp[(D_ / 4) * (3 * H_)];
__device__ float4 g_woutp[(H_ / 4) * H_];
__device__ float g_dt[T_];

#define N_W1 ((H_ / 4) * H_)
#define N_WHH ((H_ / 4) * (3 * H_))
#define N_WIH ((D_ / 4) * (3 * H_))
#define PK_TOTAL (3 * N_W1 + N_WHH + N_WIH)

__global__ void pack_all_kernel(const float* __restrict__ w1,
                                const float* __restrict__ w2,
                                const float* __restrict__ whh,
                                const float* __restrict__ wih,
                                const float* __restrict__ wout,
                                const float* __restrict__ tps) {
    int idx = blockIdx.x * blockDim.x + threadIdx.x;
    if (idx < T_) {
        g_dt[idx] = (idx == 0) ? (tps[0] - (tps[0] - 0.01f))
                               : (tps[idx] - tps[idx - 1]);
    }
    if (idx >= PK_TOTAL) return;
    const float* src; float4* dst; int O, K, local = idx;
    if (local < N_W1) { src = w1; dst = g_w1p; O = H_; K = H_; }
    else if ((local -= N_W1) < N_W1) { src = w2; dst = g_w2p; O = H_; K = H_; }
    else if ((local -= N_W1) < N_WHH) { src = whh; dst = g_whhp; O = 3 * H_; K = H_; }
    else if ((local -= N_WHH) < N_WIH) { src = wih; dst = g_wihp; O = 3 * H_; K = D_; }
    else { local -= N_WIH; src = wout; dst = g_woutp; O = H_; K = H_; }
    int k4 = local / O;
    int o = local % O;
    const float* s = src + (size_t)o * K + 4 * k4;
    dst[local] = make_float4(s[0], s[1], s[2], s[3]);
}

typedef unsigned long long ull;
__device__ __forceinline__ ull ffma2(ull a, ull b, ull c) {
    ull d; asm("fma.rn.f32x2 %0, %1, %2, %3;" : "=l"(d) : "l"(a), "l"(b), "l"(c)); return d;
}
__device__ __forceinline__ float hadd2(ull v) {
    float2 f; asm("mov.b64 {%0, %1}, %2;" : "=f"(f.x), "=f"(f.y) : "l"(v));
    return f.x + f.y;
}
__device__ __forceinline__ float sigmoidf_(float v) { return 1.0f / (1.0f + expf(-v)); }

__device__ __forceinline__ void sts_peer_f32(const void* laddr, uint32_t peer, float v) {
    uint32_t la = (uint32_t)__cvta_generic_to_shared(laddr), ra;
    asm("mapa.shared::cluster.u32 %0, %1, %2;" : "=r"(ra) : "r"(la), "r"(peer));
    asm volatile("st.shared::cluster.b32 [%0], %1;" :: "r"(ra), "r"(__float_as_uint(v)) : "memory");
}
__device__ __forceinline__ void cluster_sync_() {
    asm volatile("barrier.cluster.arrive.aligned;" ::: "memory");
    asm volatile("barrier.cluster.wait.aligned;" ::: "memory");
}

// k-packed GEMM for 4 rows: acc[rr] (f32x2 over k-parity) += W[col][k]*v[rbase+rr][k]
__device__ __forceinline__ void gemm4(ull acc[4], const ulonglong2* __restrict__ wu,
                                      int stride, int col,
                                      const float* __restrict__ vbuf, int vstride,
                                      int rbase, int kb, int nkk) {
#pragma unroll 4
    for (int kk = 0; kk < nkk; kk++) {
        int k4 = kb + kk;
        ulonglong2 w = wu[(size_t)k4 * stride + col];
#pragma unroll
        for (int rr = 0; rr < 4; rr++) {
            ulonglong2 v = *reinterpret_cast<const ulonglong2*>(
                vbuf + (size_t)(rbase + rr) * vstride + 4 * k4);
            acc[rr] = ffma2(w.x, v.x, acc[rr]);
            acc[rr] = ffma2(w.y, v.y, acc[rr]);
        }
    }
}

#define PART(slot, j) spart[(slot) * JH + (j)]

__global__ void __launch_bounds__(THREADS, 1) __cluster_dims__(2, 1, 1)
gruode_kernel(const float* __restrict__ x,
              const float* __restrict__ mask,
              const float* __restrict__ b_ih,
              const float* __restrict__ b_hh,
              const float* __restrict__ b1,
              const float* __restrict__ b2,
              const float* __restrict__ b_out,
              float* __restrict__ out) {
    __shared__ __align__(16) float hbuf[ROWSC][H_];
    __shared__ __align__(16) float odebuf[ROWSC][H_];
    __shared__ __align__(16) float a1buf[ROWSC][H_];
    __shared__ __align__(16) float xbuf[ROWSC][D_];
    __shared__ float smk[ROWSC];
    __shared__ float spart[32 * JH];   // 16KB partial-exchange

    const ulonglong2* w1u = reinterpret_cast<const ulonglong2*>(g_w1p);
    const ulonglong2* w2u = reinterpret_cast<const ulonglong2*>(g_w2p);
    const ulonglong2* whhu = reinterpret_cast<const ulonglong2*>(g_whhp);
    const ulonglong2* wihu = reinterpret_cast<const ulonglong2*>(g_wihp);
    const ulonglong2* woutu = reinterpret_cast<const ulonglong2*>(g_woutp);

    const int tid = threadIdx.x;
    const int j0 = tid & (JH - 1);
    const int kh = (tid >> 7) & 1;     // k-half
    const int pg = (tid >> 8) & 1;     // row group: rows 4*pg .. 4*pg+3
    const int rbase = 4 * pg;
    uint32_t rank;
    asm("mov.u32 %0, %%cluster_ctarank;" : "=r"(rank));
    const uint32_t peer = rank ^ 1u;
    const int jg = (int)rank * JH + j0;
    const int row0 = (blockIdx.x >> 1) * ROWSC;
    const int kb = kh * 32;            // quads base for H-dim (32 quads each half)
    const int kbx = kh * 8;            // quads base for D-dim (8 quads each half)
    const bool comb = (kh == 0);

    for (int idx = tid; idx < ROWSC * H_; idx += THREADS) (&hbuf[0][0])[idx] = 0.0f;

    float hcur[4], hlast[4], seen[4], hode[4];
#pragma unroll
    for (int r = 0; r < 4; r++) { hcur[r] = 0.0f; hlast[r] = 0.0f; seen[r] = 0.0f; hode[r] = 0.0f; }

    const float b1j = b1[jg];
    const float b2j = b2[jg];
    const float brz_r = b_ih[jg] + b_hh[jg];
    const float brz_z = b_ih[H_ + jg] + b_hh[H_ + jg];
    const float bin_ = b_ih[2 * H_ + jg];
    const float bhn = b_hh[2 * H_ + jg];

    cluster_sync_();

    for (int t = 0; t < T_; t++) {
        // ---- stage 1: x_t + mask ----
        {
            int r = tid >> 6, c = tid & 63;
            xbuf[r][c] = x[((size_t)(row0 + r) * T_ + t) * D_ + c];
        }
        if (tid < ROWSC) smk[tid] = mask[(size_t)(row0 + tid) * T_ + t];

        // ---- stage 2: a1 = tanh(h @ w1^T + b1) ----
        {
            ull acc[4] = {0ull, 0ull, 0ull, 0ull};
            gemm4(acc, w1u, H_, jg, &hbuf[0][0], H_, rbase, kb, 32);
            float hs[4];
#pragma unroll
            for (int rr = 0; rr < 4; rr++) hs[rr] = hadd2(acc[rr]);
            if (!comb) {
#pragma unroll
                for (int rr = 0; rr < 4; rr++) PART(rbase + rr, j0) = hs[rr];
            }
            __syncthreads();
            if (comb) {
#pragma unroll
                for (int rr = 0; rr < 4; rr++) {
                    int r = rbase + rr;
                    float a = tanhf(b1j + hs[rr] + PART(r, j0));
                    a1buf[r][jg] = a;
                    sts_peer_f32(&a1buf[r][jg], peer, a);
                }
            }
        }
        cluster_sync_();

        // ---- stage 3: f = a1 @ w2^T + b2 ; euler ; h_ode ----
        {
            ull acc[4] = {0ull, 0ull, 0ull, 0ull};
            gemm4(acc, w2u, H_, jg, &a1buf[0][0], H_, rbase, kb, 32);
            float hs[4];
#pragma unroll
            for (int rr = 0; rr < 4; rr++) hs[rr] = hadd2(acc[rr]);
            if (!comb) {
#pragma unroll
                for (int rr = 0; rr < 4; rr++) PART(rbase + rr, j0) = hs[rr];
            }
            __syncthreads();
            if (comb) {
                const float dtv = g_dt[t];
#pragma unroll
                for (int rr = 0; rr < 4; rr++) {
                    int r = rbase + rr;
                    float f = b2j + hs[rr] + PART(r, j0);
                    float he = hcur[rr] + dtv * f;
                    float ho = (seen[rr] > 0.0f) ? he : hcur[rr];
                    hode[rr] = ho;
                    odebuf[r][jg] = ho;
                    sts_peer_f32(&odebuf[r][jg], peer, ho);
                }
            }
        }
        cluster_sync_();

        // ---- stage 4: gates (two passes, one barrier) ----
        {
            float hsR[4], hsZ[4], hsN[4], hsI[4];
            // pass A: r and z (gi+gh fused)
            {
                ull aR[4] = {0ull, 0ull, 0ull, 0ull};
                ull aZ[4] = {0ull, 0ull, 0ull, 0ull};
#pragma unroll 4
                for (int kk = 0; kk < 32; kk++) {
                    int k4 = kb + kk;
                    ulonglong2 wr = whhu[(size_t)k4 * (3 * H_) + jg];
                    ulonglong2 wz = whhu[(size_t)k4 * (3 * H_) + H_ + jg];
#pragma unroll
                    for (int rr = 0; rr < 4; rr++) {
                        ulonglong2 v = *reinterpret_cast<const ulonglong2*>(&odebuf[rbase + rr][4 * k4]);
                        aR[rr] = ffma2(wr.x, v.x, aR[rr]); aR[rr] = ffma2(wr.y, v.y, aR[rr]);
                        aZ[rr] = ffma2(wz.x, v.x, aZ[rr]); aZ[rr] = ffma2(wz.y, v.y, aZ[rr]);
                    }
                }
#pragma unroll
                for (int kk = 0; kk < 8; kk++) {
                    int k4 = kbx + kk;
                    ulonglong2 wr = wihu[(size_t)k4 * (3 * H_) + jg];
                    ulonglong2 wz = wihu[(size_t)k4 * (3 * H_) + H_ + jg];
#pragma unroll
                    for (int rr = 0; rr < 4; rr++) {
                        ulonglong2 v = *reinterpret_cast<const ulonglong2*>(&xbuf[rbase + rr][4 * k4]);
                        aR[rr] = ffma2(wr.x, v.x, aR[rr]); aR[rr] = ffma2(wr.y, v.y, aR[rr]);
                        aZ[rr] = ffma2(wz.x, v.x, aZ[rr]); aZ[rr] = ffma2(wz.y, v.y, aZ[rr]);
                    }
                }
#pragma unroll
                for (int rr = 0; rr < 4; rr++) { hsR[rr] = hadd2(aR[rr]); hsZ[rr] = hadd2(aZ[rr]); }
            }
            // pass B: n gate — gh_n and gi_n separate
            {
                ull aN[4] = {0ull, 0ull, 0ull, 0ull};
                ull aI[4] = {0ull, 0ull, 0ull, 0ull};
                gemm4(aN, whhu, 3 * H_, 2 * H_ + jg, &odebuf[0][0], H_, rbase, kb, 32);
                gemm4(aI, wihu, 3 * H_, 2 * H_ + jg, &xbuf[0][0], D_, rbase, kbx, 8);
#pragma unroll
                for (int rr = 0; rr < 4; rr++) { hsN[rr] = hadd2(aN[rr]); hsI[rr] = hadd2(aI[rr]); }
            }
            if (!comb) {
#pragma unroll
                for (int rr = 0; rr < 4; rr++) {
                    int r = rbase + rr;
                    PART(r, j0) = hsR[rr];
                    PART(8 + r, j0) = hsZ[rr];
                    PART(16 + r, j0) = hsN[rr];
                    PART(24 + r, j0) = hsI[rr];
                }
            }
            __syncthreads();
            if (comb) {
#pragma unroll
                for (int rr = 0; rr < 4; rr++) {
                    int r = rbase + rr;
                    float fr = brz_r + hsR[rr] + PART(r, j0);
                    float fz = brz_z + hsZ[rr] + PART(8 + r, j0);
                    float fn = bhn + hsN[rr] + PART(16 + r, j0);
                    float fi = bin_ + hsI[rr] + PART(24 + r, j0);
                    float rg = sigmoidf_(fr);
                    float zg = sigmoidf_(fz);
                    float ng = tanhf(fi + rg * fn);
                    float hrnn = (1.0f - zg) * ng + zg * hode[rr];
                    float m = smk[r];
                    float hn = (m > 0.5f) ? hrnn : hode[rr];
                    hcur[rr] = hn;
                    hlast[rr] = (m > 0.5f) ? hn : hlast[rr];
                    seen[rr] = fmaxf(seen[rr], m);
                    hbuf[r][jg] = hn;
                    sts_peer_f32(&hbuf[r][jg], peer, hn);
                }
            }
        }
        cluster_sync_();
    }

    // ---- final projection: out = h_last @ w_out^T + b_out ----
    if (comb) {
#pragma unroll
        for (int rr = 0; rr < 4; rr++) {
            int r = rbase + rr;
            hbuf[r][jg] = hlast[rr];
            sts_peer_f32(&hbuf[r][jg], peer, hlast[rr]);
        }
    }
    cluster_sync_();
    {
        ull acc[4] = {0ull, 0ull, 0ull, 0ull};
        gemm4(acc, woutu, H_, jg, &hbuf[0][0], H_, rbase, kb, 32);
        float hs[4];
#pragma unroll
        for (int rr = 0; rr < 4; rr++) hs[rr] = hadd2(acc[rr]);
        if (!comb) {
#pragma unroll
            for (int rr = 0; rr < 4; rr++) PART(rbase + rr, j0) = hs[rr];
        }
        __syncthreads();
        if (comb) {
            const float bo = b_out[jg];
#pragma unroll
            for (int rr = 0; rr < 4; rr++) {
                int r = rbase + rr;
                out[(size_t)(row0 + r) * H_ + jg] = bo + hs[rr] + PART(r, j0);
            }
        }
    }
    cluster_sync_();
}

extern "C" void kernel_launch(void* const* d_in, const int* in_sizes, int n_in,
                              void* d_out, int out_size) {
    const float* x     = (const float*)d_in[0];
    const float* tps   = (const float*)d_in[1];
    const float* mask  = (const float*)d_in[2];
    const float* w_ih  = (const float*)d_in[3];
    const float* w_hh  = (const float*)d_in[4];
    const float* b_ih  = (const float*)d_in[5];
    const float* b_hh  = (const float*)d_in[6];
    const float* w1    = (const float*)d_in[7];
    const float* b1    = (const float*)d_in[8];
    const float* w2    = (const float*)d_in[9];
    const float* b2    = (const float*)d_in[10];
    const float* w_out = (const float*)d_in[11];
    const float* b_out = (const float*)d_in[12];
    float* out = (float*)d_out;

    pack_all_kernel<<<(PK_TOTAL + 255) / 256, 256>>>(w1, w2, w_hh, w_ih, w_out, tps);
    gruode_kernel<<<NCTA, THREADS>>>(x, mask, b_ih, b_hh, b1, b2, b_out, out);
}